// round 2
// baseline (speedup 1.0000x reference)
#include <cuda_runtime.h>
#include <math.h>
#include <stdint.h>

// Problem constants
#define BB    2
#define TT    2048
#define CCd   1024
#define NHh   16
#define NKVh  4
#define HDd   64
#define MMem  64
#define SSs   (MMem + TT)   // 2112

// Scratch (device globals; allocation-free per harness rules)
__device__ float g_qt[BB*TT*NHh*HDd];    // QKV gemm outs: [B*T][1024]
__device__ float g_kt[BB*TT*NKVh*HDd];   // [B*T][256]
__device__ float g_vt[BB*TT*NKVh*HDd];   // [B*T][256]
__device__ float g_q [BB*NHh*TT*HDd];    // [b][h][t][d]
__device__ float g_kf[BB*NKVh*SSs*HDd];  // [b][kv][s][d]  (mem ++ rope/rms k)
__device__ float g_vf[BB*NKVh*SSs*HDd];  // [b][kv][s][d]
__device__ float g_y [BB*TT*NHh*HDd];    // attn out [B*T][1024]

// ---------------------------------------------------------------------------
// NT SGEMM: C[m][n] = sum_k A[m][k] * Bw[n][k].  M,N multiples of 128, K mult of 16.
// 128x128 block tile, 256 threads, 8x8 per thread, K-tile 16.
// ---------------------------------------------------------------------------
__global__ __launch_bounds__(256) void sgemm_nt(
    const float* __restrict__ A, const float* __restrict__ Bw,
    float* __restrict__ Cm, int N, int K)
{
    __shared__ float As[16][132];
    __shared__ float Bs[16][132];
    const int tid = threadIdx.x;
    const int tx = tid & 15, ty = tid >> 4;
    const int m0 = blockIdx.y * 128;
    const int n0 = blockIdx.x * 128;

    float acc[8][8];
#pragma unroll
    for (int i = 0; i < 8; i++)
#pragma unroll
        for (int j = 0; j < 8; j++) acc[i][j] = 0.0f;

    for (int k0 = 0; k0 < K; k0 += 16) {
#pragma unroll
        for (int q = 0; q < 2; q++) {
            int idx = tid + q * 256;
            int r  = idx >> 2;
            int kv = (idx & 3) << 2;
            float4 a = *(const float4*)(A  + (size_t)(m0 + r) * K + k0 + kv);
            As[kv+0][r] = a.x; As[kv+1][r] = a.y; As[kv+2][r] = a.z; As[kv+3][r] = a.w;
            float4 b = *(const float4*)(Bw + (size_t)(n0 + r) * K + k0 + kv);
            Bs[kv+0][r] = b.x; Bs[kv+1][r] = b.y; Bs[kv+2][r] = b.z; Bs[kv+3][r] = b.w;
        }
        __syncthreads();
#pragma unroll
        for (int k = 0; k < 16; k++) {
            float a[8], b[8];
            *(float4*)(a)     = *(const float4*)&As[k][ty*8];
            *(float4*)(a + 4) = *(const float4*)&As[k][ty*8 + 4];
            *(float4*)(b)     = *(const float4*)&Bs[k][tx*8];
            *(float4*)(b + 4) = *(const float4*)&Bs[k][tx*8 + 4];
#pragma unroll
            for (int i = 0; i < 8; i++)
#pragma unroll
                for (int j = 0; j < 8; j++)
                    acc[i][j] = fmaf(a[i], b[j], acc[i][j]);
        }
        __syncthreads();
    }
#pragma unroll
    for (int i = 0; i < 8; i++) {
        float4 v0 = make_float4(acc[i][0], acc[i][1], acc[i][2], acc[i][3]);
        float4 v1 = make_float4(acc[i][4], acc[i][5], acc[i][6], acc[i][7]);
        float* cp = Cm + (size_t)(m0 + ty*8 + i) * N + n0 + tx*8;
        *(float4*)(cp)     = v0;
        *(float4*)(cp + 4) = v1;
    }
}

// ---------------------------------------------------------------------------
// Postprocess: warp per (row, head) item.
//  Q:   rope + rms * 1.2  -> g_q   [b][h][t][d]
//  K:   rope + rms * 1.2  -> g_kf  [b][kv][M+t][d]
//  V:   v + gate*ve       -> g_vf  [b][kv][M+t][d]   (gate = 3*sigmoid(x[:,:32]@Wg^T))
//  MEM: rms(mem_k)*1.2 -> g_kf[..][j][d]; mem_v*v_scale -> g_vf
// ---------------------------------------------------------------------------
__device__ __forceinline__ float warpsum32(float v) {
#pragma unroll
    for (int o = 16; o > 0; o >>= 1) v += __shfl_xor_sync(0xffffffffu, v, o);
    return v;
}

__global__ void postproc(const float* __restrict__ x,   const float* __restrict__ ve,
                         const float* __restrict__ cosT,const float* __restrict__ sinT,
                         const float* __restrict__ Wg,  const float* __restrict__ memk,
                         const float* __restrict__ memv,const float* __restrict__ vscale)
{
    const int g    = blockIdx.x * blockDim.x + threadIdx.x;
    const int w    = g >> 5;
    const int lane = g & 31;
    const int NQ = BB*TT*NHh;
    const int NK = BB*TT*NKVh;
    const int NV = NK;

    if (w < NQ) {
        int h = w % NHh; int t = (w / NHh) % TT; int b = w / (NHh * TT);
        const float* src = g_qt + (size_t)(b*TT + t) * CCd + h * HDd;
        float x1 = src[lane], x2 = src[lane + 32];
        float c = cosT[t*32 + lane], s = sinT[t*32 + lane];
        float o1 = x1*c - x2*s, o2 = x1*s + x2*c;
        float ss = warpsum32(o1*o1 + o2*o2);
        float r = rsqrtf(ss * (1.0f/HDd) + 1e-6f) * 1.2f;
        float* dst = g_q + (size_t)((b*NHh + h)*TT + t) * HDd;
        dst[lane] = o1*r; dst[lane + 32] = o2*r;
    } else if (w < NQ + NK) {
        int w2 = w - NQ;
        int n = w2 % NKVh; int t = (w2 / NKVh) % TT; int b = w2 / (NKVh * TT);
        const float* src = g_kt + (size_t)(b*TT + t) * (NKVh*HDd) + n * HDd;
        float x1 = src[lane], x2 = src[lane + 32];
        float c = cosT[t*32 + lane], s = sinT[t*32 + lane];
        float o1 = x1*c - x2*s, o2 = x1*s + x2*c;
        float ss = warpsum32(o1*o1 + o2*o2);
        float r = rsqrtf(ss * (1.0f/HDd) + 1e-6f) * 1.2f;
        float* dst = g_kf + (size_t)((b*NKVh + n)*SSs + (MMem + t)) * HDd;
        dst[lane] = o1*r; dst[lane + 32] = o2*r;
    } else if (w < NQ + NK + NV) {
        int w3 = w - NQ - NK;
        int n = w3 % NKVh; int t = (w3 / NKVh) % TT; int b = w3 / (NKVh * TT);
        // gate = 3*sigmoid( dot(x[b,t,:32], Wg[n,:]) )
        float gp = x[(size_t)(b*TT + t)*CCd + lane] * Wg[n*32 + lane];
        float dot = warpsum32(gp);
        float gate = 3.0f / (1.0f + __expf(-dot));
        const float* src = g_vt + (size_t)(b*TT + t) * (NKVh*HDd) + n * HDd;
        const float* vep = ve  + (size_t)(b*TT + t) * (NKVh*HDd) + n * HDd;
        float o1 = src[lane]      + gate * vep[lane];
        float o2 = src[lane + 32] + gate * vep[lane + 32];
        float* dst = g_vf + (size_t)((b*NKVh + n)*SSs + (MMem + t)) * HDd;
        dst[lane] = o1; dst[lane + 32] = o2;
    } else {
        int w4 = w - NQ - NK - NV;   // 0 .. BB*MMem*NKVh-1
        int n = w4 % NKVh; int j = (w4 / NKVh) % MMem; int b = w4 / (NKVh * MMem);
        const float* mkp = memk + (size_t)(j*NKVh + n) * HDd;
        float x1 = mkp[lane], x2 = mkp[lane + 32];
        float ss = warpsum32(x1*x1 + x2*x2);
        float r = rsqrtf(ss * (1.0f/HDd) + 1e-6f) * 1.2f;
        float* kd = g_kf + (size_t)((b*NKVh + n)*SSs + j) * HDd;
        kd[lane] = x1*r; kd[lane + 32] = x2*r;
        const float* mvp = memv + (size_t)(j*NKVh + n) * HDd;
        float vs = vscale[0];
        float* vd = g_vf + (size_t)((b*NKVh + n)*SSs + j) * HDd;
        vd[lane] = mvp[lane] * vs; vd[lane + 32] = mvp[lane + 32] * vs;
    }
}

// ---------------------------------------------------------------------------
// Flash attention, fp32. Block = (q-tile of 64, head, batch). 256 threads,
// 4x4 per thread on a 64x64 tile. Key tiles of 64: tile 0 = memory (fully
// visible), tiles 1..qi are fully-valid causal, tile qi+1 is the diagonal
// (lower-triangular mask). K smem aliased with P smem (48 KB static total).
// ---------------------------------------------------------------------------
__global__ __launch_bounds__(256) void attn_kernel()
{
    __shared__ float Qts[64*64];   // [d][r]
    __shared__ float Vs [64*64];   // [c][d]
    __shared__ float KP [64*64];   // K as [d][c], then reused as P [r][c]

    const int tid = threadIdx.x;
    const int tx = tid & 15, ty = tid >> 4;
    const int qi = blockIdx.x, h = blockIdx.y, b = blockIdx.z;
    const int t0 = qi * 64;
    const int kvh = h >> 2;   // NH/NKV = 4

    const float* qbase = g_q  + (size_t)(b*NHh  + h  ) * TT  * HDd;
    const float* kbase = g_kf + (size_t)(b*NKVh + kvh) * SSs * HDd;
    const float* vbase = g_vf + (size_t)(b*NKVh + kvh) * SSs * HDd;

    {   // load Q tile transposed: Qts[d][r]
        int r = tid >> 2, dv = tid & 3;
        const float* qr = qbase + (size_t)(t0 + r) * HDd;
#pragma unroll
        for (int u = 0; u < 4; u++) {
            int d0 = (dv + u*4) * 4;
            float4 v = *(const float4*)(qr + d0);
            Qts[(d0+0)*64 + r] = v.x; Qts[(d0+1)*64 + r] = v.y;
            Qts[(d0+2)*64 + r] = v.z; Qts[(d0+3)*64 + r] = v.w;
        }
    }

    float acc[4][4];
    float mrow[4], lrow[4];
#pragma unroll
    for (int i = 0; i < 4; i++) {
        mrow[i] = -INFINITY; lrow[i] = 0.0f;
#pragma unroll
        for (int j = 0; j < 4; j++) acc[i][j] = 0.0f;
    }

    const int nkt = qi + 2;
    for (int kt = 0; kt < nkt; kt++) {
        __syncthreads();   // previous iteration's reads of KP/Vs complete
        {   // load K tile transposed into KP, V tile direct into Vs
            int r = tid >> 2, dv = tid & 3;
            const float* kr = kbase + (size_t)(kt*64 + r) * HDd;
            const float* vr = vbase + (size_t)(kt*64 + r) * HDd;
#pragma unroll
            for (int u = 0; u < 4; u++) {
                int d0 = (dv + u*4) * 4;
                float4 kv4 = *(const float4*)(kr + d0);
                KP[(d0+0)*64 + r] = kv4.x; KP[(d0+1)*64 + r] = kv4.y;
                KP[(d0+2)*64 + r] = kv4.z; KP[(d0+3)*64 + r] = kv4.w;
                *(float4*)&Vs[r*64 + d0] = *(const float4*)(vr + d0);
            }
        }
        __syncthreads();

        // S = Q K^T
        float sc[4][4];
#pragma unroll
        for (int i = 0; i < 4; i++)
#pragma unroll
            for (int j = 0; j < 4; j++) sc[i][j] = 0.0f;
#pragma unroll 16
        for (int d = 0; d < 64; d++) {
            float qa[4], ka[4];
            *(float4*)qa = *(const float4*)&Qts[d*64 + ty*4];
            *(float4*)ka = *(const float4*)&KP [d*64 + tx*4];
#pragma unroll
            for (int i = 0; i < 4; i++)
#pragma unroll
                for (int j = 0; j < 4; j++)
                    sc[i][j] = fmaf(qa[i], ka[j], sc[i][j]);
        }

        const bool diag = (kt == nkt - 1);
#pragma unroll
        for (int i = 0; i < 4; i++)
#pragma unroll
            for (int j = 0; j < 4; j++) {
                float v = sc[i][j] * 0.125f;
                if (diag && (tx*4 + j) > (ty*4 + i)) v = -INFINITY;
                sc[i][j] = v;
            }

        // online softmax update (row stats reduced across the 16 tx lanes)
#pragma unroll
        for (int i = 0; i < 4; i++) {
            float tm = fmaxf(fmaxf(sc[i][0], sc[i][1]), fmaxf(sc[i][2], sc[i][3]));
#pragma unroll
            for (int o = 8; o > 0; o >>= 1)
                tm = fmaxf(tm, __shfl_xor_sync(0xffffffffu, tm, o, 16));
            float mn = fmaxf(mrow[i], tm);
            float scale = __expf(mrow[i] - mn);   // exp(-inf)=0 on first tile
            mrow[i] = mn;
            lrow[i] *= scale;
#pragma unroll
            for (int j = 0; j < 4; j++) acc[i][j] *= scale;
            float rs = 0.0f;
#pragma unroll
            for (int j = 0; j < 4; j++) {
                float p = __expf(sc[i][j] - mn);  // masked -> exp(-inf)=0
                sc[i][j] = p; rs += p;
            }
#pragma unroll
            for (int o = 8; o > 0; o >>= 1)
                rs += __shfl_xor_sync(0xffffffffu, rs, o, 16);
            lrow[i] += rs;
        }

        __syncthreads();   // all threads finished reading KP as K
#pragma unroll
        for (int i = 0; i < 4; i++)
            *(float4*)&KP[(ty*4 + i)*64 + tx*4] =
                make_float4(sc[i][0], sc[i][1], sc[i][2], sc[i][3]);
        __syncthreads();

        // O += P V
#pragma unroll 8
        for (int c = 0; c < 64; c++) {
            float4 vv = *(const float4*)&Vs[c*64 + tx*4];
#pragma unroll
            for (int i = 0; i < 4; i++) {
                float p = KP[(ty*4 + i)*64 + c];
                acc[i][0] = fmaf(p, vv.x, acc[i][0]);
                acc[i][1] = fmaf(p, vv.y, acc[i][1]);
                acc[i][2] = fmaf(p, vv.z, acc[i][2]);
                acc[i][3] = fmaf(p, vv.w, acc[i][3]);
            }
        }
    }

#pragma unroll
    for (int i = 0; i < 4; i++) {
        float inv = 1.0f / lrow[i];
        float4 o = make_float4(acc[i][0]*inv, acc[i][1]*inv, acc[i][2]*inv, acc[i][3]*inv);
        *(float4*)(g_y + (size_t)(b*TT + t0 + ty*4 + i) * CCd + h*HDd + tx*4) = o;
    }
}

// ---------------------------------------------------------------------------
extern "C" void kernel_launch(void* const* d_in, const int* in_sizes, int n_in,
                              void* d_out, int out_size)
{
    const float* x      = (const float*)d_in[0];
    const float* ve     = (const float*)d_in[1];
    const float* cosT   = (const float*)d_in[2];
    const float* sinT   = (const float*)d_in[3];
    const float* Wq     = (const float*)d_in[4];
    const float* Wk     = (const float*)d_in[5];
    const float* Wv     = (const float*)d_in[6];
    const float* Wproj  = (const float*)d_in[7];
    const float* Wg     = (const float*)d_in[8];
    const float* memk   = (const float*)d_in[9];
    const float* memv   = (const float*)d_in[10];
    const float* vscale = (const float*)d_in[11];
    float* out = (float*)d_out;

    void *p_qt, *p_kt, *p_vt, *p_y;
    cudaGetSymbolAddress(&p_qt, g_qt);
    cudaGetSymbolAddress(&p_kt, g_kt);
    cudaGetSymbolAddress(&p_vt, g_vt);
    cudaGetSymbolAddress(&p_y,  g_y);

    const int Mrows = BB * TT;   // 4096

    // QKV projections
    sgemm_nt<<<dim3(CCd/128, Mrows/128), 256>>>(x, Wq, (float*)p_qt, CCd, CCd);
    sgemm_nt<<<dim3((NKVh*HDd)/128, Mrows/128), 256>>>(x, Wk, (float*)p_kt, NKVh*HDd, CCd);
    sgemm_nt<<<dim3((NKVh*HDd)/128, Mrows/128), 256>>>(x, Wv, (float*)p_vt, NKVh*HDd, CCd);

    // RoPE + RMS + gate + memory concat
    {
        const int nwarps = BB*TT*NHh + BB*TT*NKVh + BB*TT*NKVh + BB*MMem*NKVh;  // 98816
        postproc<<<(nwarps * 32) / 256, 256>>>(x, ve, cosT, sinT, Wg, memk, memv, vscale);
    }

    // Flash attention
    attn_kernel<<<dim3(TT/64, NHh, BB), 256>>>();

    // Output projection
    sgemm_nt<<<dim3(CCd/128, Mrows/128), 256>>>((const float*)p_y, Wproj, out, CCd, CCd);
}

// round 4
// speedup vs baseline: 2.5605x; 2.5605x over previous
#include <cuda_runtime.h>
#include <math.h>
#include <stdint.h>

// Problem constants
#define BB    2
#define TT    2048
#define CCd   1024
#define NHh   16
#define NKVh  4
#define HDd   64
#define MMem  64
#define SSs   (MMem + TT)   // 2112

// Scratch (device globals; allocation-free per harness rules)
__device__ float g_qt[BB*TT*NHh*HDd];    // QKV gemm outs: [B*T][1024]
__device__ float g_kt[BB*TT*NKVh*HDd];   // [B*T][256]
__device__ float g_vt[BB*TT*NKVh*HDd];   // [B*T][256]
__device__ float g_q [BB*NHh*TT*HDd];    // [b][h][t][d]
__device__ float g_kf[BB*NKVh*SSs*HDd];  // [b][kv][s][d]  (mem ++ rope/rms k)
__device__ float g_vf[BB*NKVh*SSs*HDd];  // [b][kv][s][d]
__device__ float g_y [BB*TT*NHh*HDd];    // attn out [B*T][1024]

// ---------------------------------------------------------------------------
// TF32 helpers
// ---------------------------------------------------------------------------
__device__ __forceinline__ uint32_t f2tf(float f) {
    uint32_t u;
    asm("cvt.rna.tf32.f32 %0, %1;" : "=r"(u) : "f"(f));
    return u;
}

__device__ __forceinline__ void mma_tf32(float* c, const uint32_t* a, const uint32_t* b) {
    asm("mma.sync.aligned.m16n8k8.row.col.f32.tf32.tf32.f32 "
        "{%0,%1,%2,%3},{%4,%5,%6,%7},{%8,%9},{%0,%1,%2,%3};"
        : "+f"(c[0]), "+f"(c[1]), "+f"(c[2]), "+f"(c[3])
        : "r"(a[0]), "r"(a[1]), "r"(a[2]), "r"(a[3]), "r"(b[0]), "r"(b[1]));
}

// ---------------------------------------------------------------------------
// TF32 NT GEMM: C[m][n] = sum_k A[m][k] * Bw[n][k].
// Block 128x128, K-tile 32, 256 threads = 8 warps (4 m-stripes x 2 n-stripes),
// warp tile 32x64 (2 m-atoms x 8 n-atoms of m16n8k8).
// ---------------------------------------------------------------------------
#define LDK 36
__global__ __launch_bounds__(256) void gemm_tf32_nt(
    const float* __restrict__ A, const float* __restrict__ Bw,
    float* __restrict__ Cm, int N, int K)
{
    __shared__ uint32_t As[128*LDK];
    __shared__ uint32_t Bs[128*LDK];
    const int tid = threadIdx.x;
    const int lane = tid & 31, wid = tid >> 5;
    const int wm = wid & 3, wn = wid >> 2;
    const int g = lane >> 2, tg = lane & 3;
    const int m0 = blockIdx.y * 128;
    const int n0 = blockIdx.x * 128;

    float acc[2][8][4] = {};

    for (int k0 = 0; k0 < K; k0 += 32) {
#pragma unroll
        for (int q = 0; q < 4; q++) {
            int idx = q * 256 + tid;
            int row = idx >> 3, kc = (idx & 7) * 4;
            float4 av = *(const float4*)(A + (size_t)(m0 + row) * K + k0 + kc);
            As[row*LDK + kc + 0] = f2tf(av.x); As[row*LDK + kc + 1] = f2tf(av.y);
            As[row*LDK + kc + 2] = f2tf(av.z); As[row*LDK + kc + 3] = f2tf(av.w);
            float4 bv = *(const float4*)(Bw + (size_t)(n0 + row) * K + k0 + kc);
            Bs[row*LDK + kc + 0] = f2tf(bv.x); Bs[row*LDK + kc + 1] = f2tf(bv.y);
            Bs[row*LDK + kc + 2] = f2tf(bv.z); Bs[row*LDK + kc + 3] = f2tf(bv.w);
        }
        __syncthreads();
#pragma unroll
        for (int ks = 0; ks < 4; ks++) {
            const int kb = ks * 8;
            uint32_t a[2][4], b[8][2];
#pragma unroll
            for (int am = 0; am < 2; am++) {
                int r = wm*32 + am*16 + g;
                a[am][0] = As[r*LDK + kb + tg];
                a[am][1] = As[(r+8)*LDK + kb + tg];
                a[am][2] = As[r*LDK + kb + tg + 4];
                a[am][3] = As[(r+8)*LDK + kb + tg + 4];
            }
#pragma unroll
            for (int an = 0; an < 8; an++) {
                int c = wn*64 + an*8 + g;
                b[an][0] = Bs[c*LDK + kb + tg];
                b[an][1] = Bs[c*LDK + kb + tg + 4];
            }
#pragma unroll
            for (int am = 0; am < 2; am++)
#pragma unroll
                for (int an = 0; an < 8; an++)
                    mma_tf32(acc[am][an], a[am], b[an]);
        }
        __syncthreads();
    }

#pragma unroll
    for (int am = 0; am < 2; am++)
#pragma unroll
        for (int an = 0; an < 8; an++) {
            int r = m0 + wm*32 + am*16 + g;
            int cc = n0 + wn*64 + an*8 + tg*2;
            *(float2*)(Cm + (size_t)r*N + cc)     = make_float2(acc[am][an][0], acc[am][an][1]);
            *(float2*)(Cm + (size_t)(r+8)*N + cc) = make_float2(acc[am][an][2], acc[am][an][3]);
        }
}

// ---------------------------------------------------------------------------
// Postprocess (16us, unchanged)
// ---------------------------------------------------------------------------
__device__ __forceinline__ float warpsum32(float v) {
#pragma unroll
    for (int o = 16; o > 0; o >>= 1) v += __shfl_xor_sync(0xffffffffu, v, o);
    return v;
}

__global__ void postproc(const float* __restrict__ x,   const float* __restrict__ ve,
                         const float* __restrict__ cosT,const float* __restrict__ sinT,
                         const float* __restrict__ Wg,  const float* __restrict__ memk,
                         const float* __restrict__ memv,const float* __restrict__ vscale)
{
    const int gg   = blockIdx.x * blockDim.x + threadIdx.x;
    const int w    = gg >> 5;
    const int lane = gg & 31;
    const int NQ = BB*TT*NHh;
    const int NK = BB*TT*NKVh;
    const int NV = NK;

    if (w < NQ) {
        int h = w % NHh; int t = (w / NHh) % TT; int b = w / (NHh * TT);
        const float* src = g_qt + (size_t)(b*TT + t) * CCd + h * HDd;
        float x1 = src[lane], x2 = src[lane + 32];
        float c = cosT[t*32 + lane], s = sinT[t*32 + lane];
        float o1 = x1*c - x2*s, o2 = x1*s + x2*c;
        float ss = warpsum32(o1*o1 + o2*o2);
        float r = rsqrtf(ss * (1.0f/HDd) + 1e-6f) * 1.2f;
        float* dst = g_q + (size_t)((b*NHh + h)*TT + t) * HDd;
        dst[lane] = o1*r; dst[lane + 32] = o2*r;
    } else if (w < NQ + NK) {
        int w2 = w - NQ;
        int n = w2 % NKVh; int t = (w2 / NKVh) % TT; int b = w2 / (NKVh * TT);
        const float* src = g_kt + (size_t)(b*TT + t) * (NKVh*HDd) + n * HDd;
        float x1 = src[lane], x2 = src[lane + 32];
        float c = cosT[t*32 + lane], s = sinT[t*32 + lane];
        float o1 = x1*c - x2*s, o2 = x1*s + x2*c;
        float ss = warpsum32(o1*o1 + o2*o2);
        float r = rsqrtf(ss * (1.0f/HDd) + 1e-6f) * 1.2f;
        float* dst = g_kf + (size_t)((b*NKVh + n)*SSs + (MMem + t)) * HDd;
        dst[lane] = o1*r; dst[lane + 32] = o2*r;
    } else if (w < NQ + NK + NV) {
        int w3 = w - NQ - NK;
        int n = w3 % NKVh; int t = (w3 / NKVh) % TT; int b = w3 / (NKVh * TT);
        float gp = x[(size_t)(b*TT + t)*CCd + lane] * Wg[n*32 + lane];
        float dot = warpsum32(gp);
        float gate = 3.0f / (1.0f + __expf(-dot));
        const float* src = g_vt + (size_t)(b*TT + t) * (NKVh*HDd) + n * HDd;
        const float* vep = ve  + (size_t)(b*TT + t) * (NKVh*HDd) + n * HDd;
        float o1 = src[lane]      + gate * vep[lane];
        float o2 = src[lane + 32] + gate * vep[lane + 32];
        float* dst = g_vf + (size_t)((b*NKVh + n)*SSs + (MMem + t)) * HDd;
        dst[lane] = o1; dst[lane + 32] = o2;
    } else {
        int w4 = w - NQ - NK - NV;
        int n = w4 % NKVh; int j = (w4 / NKVh) % MMem; int b = w4 / (NKVh * MMem);
        const float* mkp = memk + (size_t)(j*NKVh + n) * HDd;
        float x1 = mkp[lane], x2 = mkp[lane + 32];
        float ss = warpsum32(x1*x1 + x2*x2);
        float r = rsqrtf(ss * (1.0f/HDd) + 1e-6f) * 1.2f;
        float* kd = g_kf + (size_t)((b*NKVh + n)*SSs + j) * HDd;
        kd[lane] = x1*r; kd[lane + 32] = x2*r;
        const float* mvp = memv + (size_t)(j*NKVh + n) * HDd;
        float vs = vscale[0];
        float* vd = g_vf + (size_t)((b*NKVh + n)*SSs + j) * HDd;
        vd[lane] = mvp[lane] * vs; vd[lane + 32] = mvp[lane + 32] * vs;
    }
}

// ---------------------------------------------------------------------------
// TF32 flash attention. Block = 128 q-rows x 64-key tiles. 8 warps, each owns
// 16 q-rows x full 64-key width (1 m-atom x 8 n-atoms). Q fragments live in
// registers for the whole block. P round-trips through warp-private smem for
// the C-frag -> A-frag layout conversion (only __syncwarp needed).
// Dynamic smem: Ks(64x68) + Vs(64x68) + Ps(128x68) u32 = 69632 B.
// ---------------------------------------------------------------------------
#define LDA 68
__global__ __launch_bounds__(256) void attn_tf32()
{
    extern __shared__ uint32_t sm[];
    uint32_t* Ks = sm;                 // [key][d]  tf32
    uint32_t* Vs = sm + 64*LDA;        // [key][d]  tf32
    uint32_t* Ps = sm + 2*64*LDA;      // [q][key]  tf32

    const int tid = threadIdx.x;
    const int lane = tid & 31, wid = tid >> 5;
    const int g = lane >> 2, tg = lane & 3;
    const int qi = (int)(gridDim.x - 1 - blockIdx.x);   // long blocks first
    const int h = blockIdx.y, b = blockIdx.z;
    const int t0 = qi * 128;
    const int kvh = h >> 2;

    const float* qptr = g_q  + (size_t)(b*NHh  + h  ) * TT  * HDd;
    const float* kptr = g_kf + (size_t)(b*NKVh + kvh) * SSs * HDd;
    const float* vptr = g_vf + (size_t)(b*NKVh + kvh) * SSs * HDd;

    // Q fragments in registers (row block = wid*16)
    const int rq1 = t0 + wid*16 + g;        // global q row for c0/c1
    uint32_t qa[8][4];
#pragma unroll
    for (int s8 = 0; s8 < 8; s8++) {
        int d0 = s8*8 + tg;
        qa[s8][0] = f2tf(qptr[(size_t)rq1*HDd + d0]);
        qa[s8][1] = f2tf(qptr[(size_t)(rq1+8)*HDd + d0]);
        qa[s8][2] = f2tf(qptr[(size_t)rq1*HDd + d0 + 4]);
        qa[s8][3] = f2tf(qptr[(size_t)(rq1+8)*HDd + d0 + 4]);
    }

    float o[8][4] = {};
    float m1 = -INFINITY, m2 = -INFINITY, l1 = 0.0f, l2 = 0.0f;

    const int nkt = 2*qi + 3;
    for (int kt = 0; kt < nkt; kt++) {
        __syncthreads();
        // load + convert K and V tiles (64 x 64 each)
#pragma unroll
        for (int q = 0; q < 4; q++) {
            int idx = q * 256 + tid;
            int row = idx >> 4, c4 = (idx & 15) * 4;
            float4 kv = *(const float4*)(kptr + (size_t)(kt*64 + row)*HDd + c4);
            Ks[row*LDA + c4 + 0] = f2tf(kv.x); Ks[row*LDA + c4 + 1] = f2tf(kv.y);
            Ks[row*LDA + c4 + 2] = f2tf(kv.z); Ks[row*LDA + c4 + 3] = f2tf(kv.w);
            float4 vv = *(const float4*)(vptr + (size_t)(kt*64 + row)*HDd + c4);
            Vs[row*LDA + c4 + 0] = f2tf(vv.x); Vs[row*LDA + c4 + 1] = f2tf(vv.y);
            Vs[row*LDA + c4 + 2] = f2tf(vv.z); Vs[row*LDA + c4 + 3] = f2tf(vv.w);
        }
        __syncthreads();

        // S = Q K^T  (warp: 16 rows x 64 keys)
        float s[8][4] = {};
#pragma unroll
        for (int s8 = 0; s8 < 8; s8++) {
            const int kb = s8 * 8;
#pragma unroll
            for (int an = 0; an < 8; an++) {
                uint32_t bb[2];
                int j = an*8 + g;
                bb[0] = Ks[j*LDA + kb + tg];
                bb[1] = Ks[j*LDA + kb + tg + 4];
                mma_tf32(s[an], qa[s8], bb);
            }
        }

        // scale + causal mask (key seq pos = kt*64 + col - M)
        const bool dg = (kt >= 2*qi + 1);
#pragma unroll
        for (int an = 0; an < 8; an++) {
            int j0 = kt*64 + an*8 + tg*2 - MMem;   // kpos of c0; c1 = j0+1
            s[an][0] *= 0.125f; s[an][1] *= 0.125f;
            s[an][2] *= 0.125f; s[an][3] *= 0.125f;
            if (dg) {
                if (j0     > rq1)   s[an][0] = -INFINITY;
                if (j0 + 1 > rq1)   s[an][1] = -INFINITY;
                if (j0     > rq1+8) s[an][2] = -INFINITY;
                if (j0 + 1 > rq1+8) s[an][3] = -INFINITY;
            }
        }

        // online softmax (rows rq1 via c0/c1, rq1+8 via c2/c3)
        float tm1 = -INFINITY, tm2 = -INFINITY;
#pragma unroll
        for (int an = 0; an < 8; an++) {
            tm1 = fmaxf(tm1, fmaxf(s[an][0], s[an][1]));
            tm2 = fmaxf(tm2, fmaxf(s[an][2], s[an][3]));
        }
        tm1 = fmaxf(tm1, __shfl_xor_sync(0xffffffffu, tm1, 1));
        tm1 = fmaxf(tm1, __shfl_xor_sync(0xffffffffu, tm1, 2));
        tm2 = fmaxf(tm2, __shfl_xor_sync(0xffffffffu, tm2, 1));
        tm2 = fmaxf(tm2, __shfl_xor_sync(0xffffffffu, tm2, 2));

        float mn1 = fmaxf(m1, tm1), mn2 = fmaxf(m2, tm2);
        float sc1 = __expf(m1 - mn1), sc2 = __expf(m2 - mn2);
        m1 = mn1; m2 = mn2;
        l1 *= sc1; l2 *= sc2;
#pragma unroll
        for (int dn = 0; dn < 8; dn++) {
            o[dn][0] *= sc1; o[dn][1] *= sc1;
            o[dn][2] *= sc2; o[dn][3] *= sc2;
        }
        float rs1 = 0.0f, rs2 = 0.0f;
#pragma unroll
        for (int an = 0; an < 8; an++) {
            s[an][0] = __expf(s[an][0] - mn1); s[an][1] = __expf(s[an][1] - mn1);
            s[an][2] = __expf(s[an][2] - mn2); s[an][3] = __expf(s[an][3] - mn2);
            rs1 += s[an][0] + s[an][1];
            rs2 += s[an][2] + s[an][3];
        }
        rs1 += __shfl_xor_sync(0xffffffffu, rs1, 1);
        rs1 += __shfl_xor_sync(0xffffffffu, rs1, 2);
        rs2 += __shfl_xor_sync(0xffffffffu, rs2, 1);
        rs2 += __shfl_xor_sync(0xffffffffu, rs2, 2);
        l1 += rs1; l2 += rs2;

        // P -> warp-private smem region (layout conversion), tf32
        {
            int pr = wid*16 + g;
#pragma unroll
            for (int an = 0; an < 8; an++) {
                int cc = an*8 + tg*2;
                *(uint2*)&Ps[pr*LDA + cc]     = make_uint2(f2tf(s[an][0]), f2tf(s[an][1]));
                *(uint2*)&Ps[(pr+8)*LDA + cc] = make_uint2(f2tf(s[an][2]), f2tf(s[an][3]));
            }
        }
        __syncwarp();

        // O += P V
        {
            int pr = wid*16 + g;
#pragma unroll
            for (int k8 = 0; k8 < 8; k8++) {
                uint32_t a[4];
                int kb = k8*8 + tg;
                a[0] = Ps[pr*LDA + kb];
                a[1] = Ps[(pr+8)*LDA + kb];
                a[2] = Ps[pr*LDA + kb + 4];
                a[3] = Ps[(pr+8)*LDA + kb + 4];
#pragma unroll
                for (int dn = 0; dn < 8; dn++) {
                    uint32_t bb[2];
                    bb[0] = Vs[(k8*8 + tg)*LDA + dn*8 + g];
                    bb[1] = Vs[(k8*8 + tg + 4)*LDA + dn*8 + g];
                    mma_tf32(o[dn], a, bb);
                }
            }
        }
    }

    // finalize: divide by l, write to g_y [b*T + t][h*64 + d]
    const float il1 = 1.0f / l1, il2 = 1.0f / l2;
    float* y1 = g_y + (size_t)(b*TT + rq1 - 0) * (NHh*HDd) + h*HDd;
    float* y2 = g_y + (size_t)(b*TT + rq1 + 8) * (NHh*HDd) + h*HDd;
#pragma unroll
    for (int dn = 0; dn < 8; dn++) {
        int cc = dn*8 + tg*2;
        *(float2*)(y1 + cc) = make_float2(o[dn][0]*il1, o[dn][1]*il1);
        *(float2*)(y2 + cc) = make_float2(o[dn][2]*il2, o[dn][3]*il2);
    }
}

// ---------------------------------------------------------------------------
extern "C" void kernel_launch(void* const* d_in, const int* in_sizes, int n_in,
                              void* d_out, int out_size)
{
    const float* x      = (const float*)d_in[0];
    const float* ve     = (const float*)d_in[1];
    const float* cosT   = (const float*)d_in[2];
    const float* sinT   = (const float*)d_in[3];
    const float* Wq     = (const float*)d_in[4];
    const float* Wk     = (const float*)d_in[5];
    const float* Wv     = (const float*)d_in[6];
    const float* Wproj  = (const float*)d_in[7];
    const float* Wg     = (const float*)d_in[8];
    const float* memk   = (const float*)d_in[9];
    const float* memv   = (const float*)d_in[10];
    const float* vscale = (const float*)d_in[11];
    float* out = (float*)d_out;

    void *p_qt, *p_kt, *p_vt, *p_y;
    cudaGetSymbolAddress(&p_qt, g_qt);
    cudaGetSymbolAddress(&p_kt, g_kt);
    cudaGetSymbolAddress(&p_vt, g_vt);
    cudaGetSymbolAddress(&p_y,  g_y);

    const int Mrows = BB * TT;   // 4096
    const int ATTN_SMEM = (64*LDA + 64*LDA + 128*LDA) * 4;  // 69632 B
    cudaFuncSetAttribute(attn_tf32, cudaFuncAttributeMaxDynamicSharedMemorySize, ATTN_SMEM);

    // QKV projections (tf32 tensor cores)
    gemm_tf32_nt<<<dim3(CCd/128, Mrows/128), 256>>>(x, Wq, (float*)p_qt, CCd, CCd);
    gemm_tf32_nt<<<dim3((NKVh*HDd)/128, Mrows/128), 256>>>(x, Wk, (float*)p_kt, NKVh*HDd, CCd);
    gemm_tf32_nt<<<dim3((NKVh*HDd)/128, Mrows/128), 256>>>(x, Wv, (float*)p_vt, NKVh*HDd, CCd);

    // RoPE + RMS + gate + memory concat
    {
        const int nwarps = BB*TT*NHh + BB*TT*NKVh + BB*TT*NKVh + BB*MMem*NKVh;  // 98816
        postproc<<<(nwarps * 32) / 256, 256>>>(x, ve, cosT, sinT, Wg, memk, memv, vscale);
    }

    // Flash attention (tf32 tensor cores)
    attn_tf32<<<dim3(TT/128, NHh, BB), 256, ATTN_SMEM>>>();

    // Output projection
    gemm_tf32_nt<<<dim3(CCd/128, Mrows/128), 256>>>((const float*)p_y, Wproj, out, CCd, CCd);
}

// round 7
// speedup vs baseline: 2.6837x; 1.0481x over previous
#include <cuda_runtime.h>
#include <cuda_fp16.h>
#include <math.h>
#include <stdint.h>

// Problem constants
#define BB    2
#define TT    2048
#define CCd   1024
#define NHh   16
#define NKVh  4
#define HDd   64
#define MMem  64
#define SSs   (MMem + TT)   // 2112

// Scratch (device globals; allocation-free per harness rules)
__device__ float g_qt[BB*TT*NHh*HDd];    // QKV gemm outs: [B*T][1024]
__device__ float g_kt[BB*TT*NKVh*HDd];   // [B*T][256]
__device__ float g_vt[BB*TT*NKVh*HDd];   // [B*T][256]
__device__ float g_q [BB*NHh*TT*HDd];    // [b][h][t][d]
__device__ float g_kf[BB*NKVh*SSs*HDd];  // [b][kv][s][d]
__device__ float g_vf[BB*NKVh*SSs*HDd];  // [b][kv][s][d]
__device__ float g_y [BB*TT*NHh*HDd];    // attn out [B*T][1024]

// ---------------------------------------------------------------------------
// fp16 helpers
// ---------------------------------------------------------------------------
__device__ __forceinline__ uint32_t h2u(__half2 h) { return *(uint32_t*)&h; }
__device__ __forceinline__ uint32_t packh(float a, float b) {
    __half2 t = __floats2half2_rn(a, b);
    return h2u(t);
}

// mma.sync m16n8k16 fp16 in, fp32 accumulate
__device__ __forceinline__ void mma_f16(float* c, const uint32_t* a, const uint32_t* b) {
    asm("mma.sync.aligned.m16n8k16.row.col.f32.f16.f16.f32 "
        "{%0,%1,%2,%3},{%4,%5,%6,%7},{%8,%9},{%0,%1,%2,%3};"
        : "+f"(c[0]), "+f"(c[1]), "+f"(c[2]), "+f"(c[3])
        : "r"(a[0]), "r"(a[1]), "r"(a[2]), "r"(a[3]), "r"(b[0]), "r"(b[1]));
}

#define LDSM_X4(r0,r1,r2,r3,addr) \
    asm volatile("ldmatrix.sync.aligned.m8n8.x4.shared.b16 {%0,%1,%2,%3}, [%4];" \
                 : "=r"(r0), "=r"(r1), "=r"(r2), "=r"(r3) : "r"(addr))
#define LDSM_X4_T(r0,r1,r2,r3,addr) \
    asm volatile("ldmatrix.sync.aligned.m8n8.x4.trans.shared.b16 {%0,%1,%2,%3}, [%4];" \
                 : "=r"(r0), "=r"(r1), "=r"(r2), "=r"(r3) : "r"(addr))

__device__ __forceinline__ uint32_t smem_u32(const void* p) {
    uint32_t a;
    asm("{ .reg .u64 t; cvta.to.shared.u64 t, %1; cvt.u32.u64 %0, t; }" : "=r"(a) : "l"(p));
    return a;
}

// ---------------------------------------------------------------------------
// fp16 NT GEMM with A-side hi/lo split (near-fp32 A precision).
// C[m][n] = sum_k A[m][k]*Bw[n][k].  Block 128x128, K-tile 32, 8 warps 4x2,
// warp tile 32x64: 2 m-atoms x 8 n-atoms of m16n8k16, 2 k16 chunks / K-tile.
// smem rows: 16 u32 (fp16x2) + 4 pad = 20 -> conflict-free fragment LDS.
// ---------------------------------------------------------------------------
#define GLD 20
__global__ __launch_bounds__(256) void gemm_f16_nt(
    const float* __restrict__ A, const float* __restrict__ Bw,
    float* __restrict__ Cm, int N, int K)
{
    __shared__ uint32_t Ah[128*GLD];
    __shared__ uint32_t Al[128*GLD];
    __shared__ uint32_t Bs[128*GLD];
    const int tid = threadIdx.x;
    const int lane = tid & 31, wid = tid >> 5;
    const int wm = wid & 3, wn = wid >> 2;
    const int g = lane >> 2, tg = lane & 3;
    const int m0 = blockIdx.y * 128;
    const int n0 = blockIdx.x * 128;

    float acc[2][8][4] = {};

    for (int k0 = 0; k0 < K; k0 += 32) {
#pragma unroll
        for (int q = 0; q < 4; q++) {
            int idx = q * 256 + tid;
            int row = idx >> 3, kq = (idx & 7) * 4;
            float4 av = *(const float4*)(A + (size_t)(m0 + row) * K + k0 + kq);
            __half2 h0 = __floats2half2_rn(av.x, av.y);
            __half2 h1 = __floats2half2_rn(av.z, av.w);
            float2 f0 = __half22float2(h0), f1 = __half22float2(h1);
            *(uint2*)&Ah[row*GLD + (kq >> 1)] = make_uint2(h2u(h0), h2u(h1));
            *(uint2*)&Al[row*GLD + (kq >> 1)] = make_uint2(
                packh(av.x - f0.x, av.y - f0.y), packh(av.z - f1.x, av.w - f1.y));
            float4 bv = *(const float4*)(Bw + (size_t)(n0 + row) * K + k0 + kq);
            *(uint2*)&Bs[row*GLD + (kq >> 1)] = make_uint2(
                packh(bv.x, bv.y), packh(bv.z, bv.w));
        }
        __syncthreads();
#pragma unroll
        for (int ks = 0; ks < 2; ks++) {
            const int kp = ks * 8;
            uint32_t ah[2][4], al[2][4], b[8][2];
#pragma unroll
            for (int am = 0; am < 2; am++) {
                int r = wm*32 + am*16 + g;
                ah[am][0] = Ah[r*GLD + kp + tg];
                ah[am][1] = Ah[(r+8)*GLD + kp + tg];
                ah[am][2] = Ah[r*GLD + kp + tg + 4];
                ah[am][3] = Ah[(r+8)*GLD + kp + tg + 4];
                al[am][0] = Al[r*GLD + kp + tg];
                al[am][1] = Al[(r+8)*GLD + kp + tg];
                al[am][2] = Al[r*GLD + kp + tg + 4];
                al[am][3] = Al[(r+8)*GLD + kp + tg + 4];
            }
#pragma unroll
            for (int an = 0; an < 8; an++) {
                int c = wn*64 + an*8 + g;
                b[an][0] = Bs[c*GLD + kp + tg];
                b[an][1] = Bs[c*GLD + kp + tg + 4];
            }
#pragma unroll
            for (int am = 0; am < 2; am++)
#pragma unroll
                for (int an = 0; an < 8; an++) {
                    mma_f16(acc[am][an], ah[am], b[an]);
                    mma_f16(acc[am][an], al[am], b[an]);
                }
        }
        __syncthreads();
    }

#pragma unroll
    for (int am = 0; am < 2; am++)
#pragma unroll
        for (int an = 0; an < 8; an++) {
            int r = m0 + wm*32 + am*16 + g;
            int cc = n0 + wn*64 + an*8 + tg*2;
            *(float2*)(Cm + (size_t)r*N + cc)     = make_float2(acc[am][an][0], acc[am][an][1]);
            *(float2*)(Cm + (size_t)(r+8)*N + cc) = make_float2(acc[am][an][2], acc[am][an][3]);
        }
}

// ---------------------------------------------------------------------------
// Postprocess (16us, unchanged)
// ---------------------------------------------------------------------------
__device__ __forceinline__ float warpsum32(float v) {
#pragma unroll
    for (int o = 16; o > 0; o >>= 1) v += __shfl_xor_sync(0xffffffffu, v, o);
    return v;
}

__global__ void postproc(const float* __restrict__ x,   const float* __restrict__ ve,
                         const float* __restrict__ cosT,const float* __restrict__ sinT,
                         const float* __restrict__ Wg,  const float* __restrict__ memk,
                         const float* __restrict__ memv,const float* __restrict__ vscale)
{
    const int gg   = blockIdx.x * blockDim.x + threadIdx.x;
    const int w    = gg >> 5;
    const int lane = gg & 31;
    const int NQ = BB*TT*NHh;
    const int NK = BB*TT*NKVh;
    const int NV = NK;

    if (w < NQ) {
        int h = w % NHh; int t = (w / NHh) % TT; int b = w / (NHh * TT);
        const float* src = g_qt + (size_t)(b*TT + t) * CCd + h * HDd;
        float x1 = src[lane], x2 = src[lane + 32];
        float c = cosT[t*32 + lane], s = sinT[t*32 + lane];
        float o1 = x1*c - x2*s, o2 = x1*s + x2*c;
        float ss = warpsum32(o1*o1 + o2*o2);
        float r = rsqrtf(ss * (1.0f/HDd) + 1e-6f) * 1.2f;
        float* dst = g_q + (size_t)((b*NHh + h)*TT + t) * HDd;
        dst[lane] = o1*r; dst[lane + 32] = o2*r;
    } else if (w < NQ + NK) {
        int w2 = w - NQ;
        int n = w2 % NKVh; int t = (w2 / NKVh) % TT; int b = w2 / (NKVh * TT);
        const float* src = g_kt + (size_t)(b*TT + t) * (NKVh*HDd) + n * HDd;
        float x1 = src[lane], x2 = src[lane + 32];
        float c = cosT[t*32 + lane], s = sinT[t*32 + lane];
        float o1 = x1*c - x2*s, o2 = x1*s + x2*c;
        float ss = warpsum32(o1*o1 + o2*o2);
        float r = rsqrtf(ss * (1.0f/HDd) + 1e-6f) * 1.2f;
        float* dst = g_kf + (size_t)((b*NKVh + n)*SSs + (MMem + t)) * HDd;
        dst[lane] = o1*r; dst[lane + 32] = o2*r;
    } else if (w < NQ + NK + NV) {
        int w3 = w - NQ - NK;
        int n = w3 % NKVh; int t = (w3 / NKVh) % TT; int b = w3 / (NKVh * TT);
        float gp = x[(size_t)(b*TT + t)*CCd + lane] * Wg[n*32 + lane];
        float dot = warpsum32(gp);
        float gate = 3.0f / (1.0f + __expf(-dot));
        const float* src = g_vt + (size_t)(b*TT + t) * (NKVh*HDd) + n * HDd;
        const float* vep = ve  + (size_t)(b*TT + t) * (NKVh*HDd) + n * HDd;
        float o1 = src[lane]      + gate * vep[lane];
        float o2 = src[lane + 32] + gate * vep[lane + 32];
        float* dst = g_vf + (size_t)((b*NKVh + n)*SSs + (MMem + t)) * HDd;
        dst[lane] = o1; dst[lane + 32] = o2;
    } else {
        int w4 = w - NQ - NK - NV;
        int n = w4 % NKVh; int j = (w4 / NKVh) % MMem; int b = w4 / (NKVh * MMem);
        const float* mkp = memk + (size_t)(j*NKVh + n) * HDd;
        float x1 = mkp[lane], x2 = mkp[lane + 32];
        float ss = warpsum32(x1*x1 + x2*x2);
        float r = rsqrtf(ss * (1.0f/HDd) + 1e-6f) * 1.2f;
        float* kd = g_kf + (size_t)((b*NKVh + n)*SSs + j) * HDd;
        kd[lane] = x1*r; kd[lane + 32] = x2*r;
        const float* mvp = memv + (size_t)(j*NKVh + n) * HDd;
        float vs = vscale[0];
        float* vd = g_vf + (size_t)((b*NKVh + n)*SSs + j) * HDd;
        vd[lane] = mvp[lane] * vs; vd[lane + 32] = mvp[lane + 32] * vs;
    }
}

// ---------------------------------------------------------------------------
// fp16 flash attention. Block = 128 q-rows x 64-key tiles, 8 warps, each warp
// owns 16 q-rows x 64 keys (m16n8k16 atoms). K and V in smem as fp16 [key][d]
// (72-half rows = 144B pitch -> conflict-free LDSM). S B-frags via ldmatrix,
// PV B-frags via ldmatrix.trans. P round-trips through packed-half2 smem.
// Static smem 36864 B.
// ---------------------------------------------------------------------------
#define KLD 36   // u32 per K/V row (32 used + 4 pad) = 72 halfs = 144 B
__global__ __launch_bounds__(256) void attn_f16()
{
    __shared__ uint32_t Ks[64*KLD];   // [key][d/2]
    __shared__ uint32_t Vs[64*KLD];   // [key][d/2]
    __shared__ uint32_t Ps[128*KLD];  // [q][key/2]

    const int tid = threadIdx.x;
    const int lane = tid & 31, wid = tid >> 5;
    const int g = lane >> 2, tg = lane & 3;
    const int qi = (int)(gridDim.x - 1 - blockIdx.x);   // long blocks first
    const int h = blockIdx.y, b = blockIdx.z;
    const int t0 = qi * 128;
    const int kvh = h >> 2;

    const float* qptr = g_q  + (size_t)(b*NHh  + h  ) * TT  * HDd;
    const float* kptr = g_kf + (size_t)(b*NKVh + kvh) * SSs * HDd;
    const float* vptr = g_vf + (size_t)(b*NKVh + kvh) * SSs * HDd;

    const uint32_t ks_b = smem_u32(Ks);
    const uint32_t vs_b = smem_u32(Vs);

    // ldmatrix lane->address components
    const int koK = (lane & 7) + ((lane & 16) >> 1);  // key offset (non-trans, K)
    const int doK = lane & 8;                          // d offset in halfs
    const int koV = lane & 15;                         // key offset (trans, V)
    const int doV = (lane & 16) >> 1;                  // d offset in halfs

    // Q fragments in registers (fp16 packed); warp rows [wid*16, wid*16+16)
    const int rq1 = t0 + wid*16 + g;
    uint32_t qa[4][4];
#pragma unroll
    for (int s8 = 0; s8 < 4; s8++) {
        int d0 = s8*16 + 2*tg;
        float2 v0 = *(const float2*)(qptr + (size_t)rq1*HDd + d0);
        float2 v1 = *(const float2*)(qptr + (size_t)(rq1+8)*HDd + d0);
        float2 v2 = *(const float2*)(qptr + (size_t)rq1*HDd + d0 + 8);
        float2 v3 = *(const float2*)(qptr + (size_t)(rq1+8)*HDd + d0 + 8);
        qa[s8][0] = packh(v0.x, v0.y);
        qa[s8][1] = packh(v1.x, v1.y);
        qa[s8][2] = packh(v2.x, v2.y);
        qa[s8][3] = packh(v3.x, v3.y);
    }

    float o[8][4] = {};
    float m1 = -INFINITY, m2 = -INFINITY, l1 = 0.0f, l2 = 0.0f;

    const int nkt = 2*qi + 3;
    for (int kt = 0; kt < nkt; kt++) {
        __syncthreads();
        // load + convert K and V tiles (64 x 64 each), fp16-packed rows
#pragma unroll
        for (int q = 0; q < 4; q++) {
            int idx = q * 256 + tid;
            int row = idx >> 4, c4 = (idx & 15) * 4;
            float4 kv = *(const float4*)(kptr + (size_t)(kt*64 + row)*HDd + c4);
            *(uint2*)&Ks[row*KLD + (c4 >> 1)] = make_uint2(packh(kv.x, kv.y), packh(kv.z, kv.w));
            float4 vv = *(const float4*)(vptr + (size_t)(kt*64 + row)*HDd + c4);
            *(uint2*)&Vs[row*KLD + (c4 >> 1)] = make_uint2(packh(vv.x, vv.y), packh(vv.z, vv.w));
        }
        __syncthreads();

        // S = Q K^T : warp computes 16 rows x 64 keys
        float s[8][4] = {};
#pragma unroll
        for (int s8 = 0; s8 < 4; s8++) {
#pragma unroll
            for (int anp = 0; anp < 4; anp++) {
                uint32_t r0, r1, r2, r3;
                uint32_t addr = ks_b + (((anp*16 + koK)*72) + s8*16 + doK) * 2;
                LDSM_X4(r0, r1, r2, r3, addr);
                uint32_t b0[2] = {r0, r1}, b1[2] = {r2, r3};
                mma_f16(s[2*anp],   qa[s8], b0);
                mma_f16(s[2*anp+1], qa[s8], b1);
            }
        }

        // scale + causal mask (key seq pos = kt*64 + col - M)
        const bool dg = (kt >= 2*qi + 1);
#pragma unroll
        for (int an = 0; an < 8; an++) {
            int j0 = kt*64 + an*8 + tg*2 - MMem;
            s[an][0] *= 0.125f; s[an][1] *= 0.125f;
            s[an][2] *= 0.125f; s[an][3] *= 0.125f;
            if (dg) {
                if (j0     > rq1)   s[an][0] = -INFINITY;
                if (j0 + 1 > rq1)   s[an][1] = -INFINITY;
                if (j0     > rq1+8) s[an][2] = -INFINITY;
                if (j0 + 1 > rq1+8) s[an][3] = -INFINITY;
            }
        }

        // online softmax (rows rq1 via c0/c1, rq1+8 via c2/c3)
        float tm1 = -INFINITY, tm2 = -INFINITY;
#pragma unroll
        for (int an = 0; an < 8; an++) {
            tm1 = fmaxf(tm1, fmaxf(s[an][0], s[an][1]));
            tm2 = fmaxf(tm2, fmaxf(s[an][2], s[an][3]));
        }
        tm1 = fmaxf(tm1, __shfl_xor_sync(0xffffffffu, tm1, 1));
        tm1 = fmaxf(tm1, __shfl_xor_sync(0xffffffffu, tm1, 2));
        tm2 = fmaxf(tm2, __shfl_xor_sync(0xffffffffu, tm2, 1));
        tm2 = fmaxf(tm2, __shfl_xor_sync(0xffffffffu, tm2, 2));

        float mn1 = fmaxf(m1, tm1), mn2 = fmaxf(m2, tm2);
        float sc1 = __expf(m1 - mn1), sc2 = __expf(m2 - mn2);
        m1 = mn1; m2 = mn2;
        l1 *= sc1; l2 *= sc2;
#pragma unroll
        for (int dn = 0; dn < 8; dn++) {
            o[dn][0] *= sc1; o[dn][1] *= sc1;
            o[dn][2] *= sc2; o[dn][3] *= sc2;
        }
        float rs1 = 0.0f, rs2 = 0.0f;
#pragma unroll
        for (int an = 0; an < 8; an++) {
            s[an][0] = __expf(s[an][0] - mn1); s[an][1] = __expf(s[an][1] - mn1);
            s[an][2] = __expf(s[an][2] - mn2); s[an][3] = __expf(s[an][3] - mn2);
            rs1 += s[an][0] + s[an][1];
            rs2 += s[an][2] + s[an][3];
        }
        rs1 += __shfl_xor_sync(0xffffffffu, rs1, 1);
        rs1 += __shfl_xor_sync(0xffffffffu, rs1, 2);
        rs2 += __shfl_xor_sync(0xffffffffu, rs2, 1);
        rs2 += __shfl_xor_sync(0xffffffffu, rs2, 2);
        l1 += rs1; l2 += rs2;

        // P -> warp-private smem rows (packed fp16x2 along keys)
        const int pr = wid*16 + g;
#pragma unroll
        for (int an = 0; an < 8; an++) {
            Ps[pr*KLD + an*4 + tg]     = packh(s[an][0], s[an][1]);
            Ps[(pr+8)*KLD + an*4 + tg] = packh(s[an][2], s[an][3]);
        }
        __syncwarp();

        // O += P V  (V B-frags via ldmatrix.trans)
#pragma unroll
        for (int k8 = 0; k8 < 4; k8++) {
            uint32_t a[4];
            a[0] = Ps[pr*KLD + k8*8 + tg];
            a[1] = Ps[(pr+8)*KLD + k8*8 + tg];
            a[2] = Ps[pr*KLD + k8*8 + tg + 4];
            a[3] = Ps[(pr+8)*KLD + k8*8 + tg + 4];
            uint32_t vrow = vs_b + (((k8*16 + koV)*72) + doV) * 2;
#pragma unroll
            for (int dnp = 0; dnp < 4; dnp++) {
                uint32_t r0, r1, r2, r3;
                LDSM_X4_T(r0, r1, r2, r3, vrow + dnp*32);
                uint32_t b0[2] = {r0, r1}, b1[2] = {r2, r3};
                mma_f16(o[2*dnp],   a, b0);
                mma_f16(o[2*dnp+1], a, b1);
            }
        }
    }

    // finalize
    const float il1 = 1.0f / l1, il2 = 1.0f / l2;
    float* y1 = g_y + (size_t)(b*TT + rq1 - 0) * (NHh*HDd) + h*HDd;
    float* y2 = g_y + (size_t)(b*TT + rq1 + 8) * (NHh*HDd) + h*HDd;
#pragma unroll
    for (int dn = 0; dn < 8; dn++) {
        int cc = dn*8 + tg*2;
        *(float2*)(y1 + cc) = make_float2(o[dn][0]*il1, o[dn][1]*il1);
        *(float2*)(y2 + cc) = make_float2(o[dn][2]*il2, o[dn][3]*il2);
    }
}

// ---------------------------------------------------------------------------
extern "C" void kernel_launch(void* const* d_in, const int* in_sizes, int n_in,
                              void* d_out, int out_size)
{
    const float* x      = (const float*)d_in[0];
    const float* ve     = (const float*)d_in[1];
    const float* cosT   = (const float*)d_in[2];
    const float* sinT   = (const float*)d_in[3];
    const float* Wq     = (const float*)d_in[4];
    const float* Wk     = (const float*)d_in[5];
    const float* Wv     = (const float*)d_in[6];
    const float* Wproj  = (const float*)d_in[7];
    const float* Wg     = (const float*)d_in[8];
    const float* memk   = (const float*)d_in[9];
    const float* memv   = (const float*)d_in[10];
    const float* vscale = (const float*)d_in[11];
    float* out = (float*)d_out;

    void *p_qt, *p_kt, *p_vt, *p_y;
    cudaGetSymbolAddress(&p_qt, g_qt);
    cudaGetSymbolAddress(&p_kt, g_kt);
    cudaGetSymbolAddress(&p_vt, g_vt);
    cudaGetSymbolAddress(&p_y,  g_y);

    const int Mrows = BB * TT;   // 4096

    // QKV projections (fp16 tensor cores, A hi/lo split)
    gemm_f16_nt<<<dim3(CCd/128, Mrows/128), 256>>>(x, Wq, (float*)p_qt, CCd, CCd);
    gemm_f16_nt<<<dim3((NKVh*HDd)/128, Mrows/128), 256>>>(x, Wk, (float*)p_kt, NKVh*HDd, CCd);
    gemm_f16_nt<<<dim3((NKVh*HDd)/128, Mrows/128), 256>>>(x, Wv, (float*)p_vt, NKVh*HDd, CCd);

    // RoPE + RMS + gate + memory concat
    {
        const int nwarps = BB*TT*NHh + BB*TT*NKVh + BB*TT*NKVh + BB*MMem*NKVh;  // 98816
        postproc<<<(nwarps * 32) / 256, 256>>>(x, ve, cosT, sinT, Wg, memk, memv, vscale);
    }

    // Flash attention (fp16 tensor cores)
    attn_f16<<<dim3(TT/128, NHh, BB), 256>>>();

    // Output projection (fp16, A hi/lo split)
    gemm_f16_nt<<<dim3(CCd/128, Mrows/128), 256>>>((const float*)p_y, Wproj, out, CCd, CCd);
}